// round 7
// baseline (speedup 1.0000x reference)
#include <cuda_runtime.h>
#include <cuda_fp16.h>
#include <cstdint>

// ============================================================================
// BSpline via warp-level mma.sync (HMMA).
//   out[b,o] = sum_{i,c} basis(x[b,i])[c] * cp[i,c,o]
//   = GEMM: A (rows x 768) * B (768 x 64), k = i*12 + c.
// R7 = R5 (16 warps/SM: M_TILE=64, THREADS=256, warp tile M16xN32, 2 CTA/SM)
//   + B repacked lane-contiguous (2 x LDG.128 per kstep, was 4 x LDG.64)
//   + paired st.shared.v2.u64 in the A-build phase.
// ============================================================================

#define DIMS 64
#define KSTEPS 48          // 768 / 16
#define M_TILE 64
#define THREADS 256

#define A_PITCH_B 1552     // bytes per A row: 776 halfs; odd multiple of 16B
#define SMEM_A_BYTES (M_TILE * A_PITCH_B)        // 99328
#define SMEM_TAB SMEM_A_BYTES
#define SMEM_TOTAL (SMEM_A_BYTES + 512)

// B fragments, lane-contiguous: g_Bf2[((ks*2+nb)*32+lid)*2+q] (uint4)
//   uint4 = { frag(n0).kq01, frag(n0).kq89, frag(n0+8).kq01, frag(n0+8).kq89 }
//   n0 = nb*32 + (lid>>2) + q*16, kq = lid&3, k0 = ks*16+kq*2.
__device__ uint4 g_Bf2[KSTEPS * 2 * 32 * 2];

static __device__ __forceinline__ uint32_t s2u(const void* p) {
    uint32_t a;
    asm("{ .reg .u64 t; cvta.to.shared.u64 t, %1; cvt.u32.u64 %0, t; }" : "=r"(a) : "l"(p));
    return a;
}

static __device__ __forceinline__ void ldsm_x4(uint32_t& r0, uint32_t& r1,
                                               uint32_t& r2, uint32_t& r3,
                                               uint32_t addr) {
    asm volatile("ldmatrix.sync.aligned.m8n8.x4.shared.b16 {%0,%1,%2,%3}, [%4];"
                 : "=r"(r0), "=r"(r1), "=r"(r2), "=r"(r3) : "r"(addr));
}

static __device__ __forceinline__ void mma16816(float& d0, float& d1, float& d2, float& d3,
                                                uint32_t a0, uint32_t a1, uint32_t a2, uint32_t a3,
                                                uint32_t b0, uint32_t b1) {
    asm("mma.sync.aligned.m16n8k16.row.col.f32.f16.f16.f32 "
        "{%0,%1,%2,%3}, {%4,%5,%6,%7}, {%8,%9}, {%0,%1,%2,%3};"
        : "+f"(d0), "+f"(d1), "+f"(d2), "+f"(d3)
        : "r"(a0), "r"(a1), "r"(a2), "r"(a3), "r"(b0), "r"(b1));
}

static __device__ __forceinline__ float knotv(int k) {
    int v = max(0, min(9, k - 3));
    return (float)v / 9.0f;
}

static __device__ __forceinline__ uint32_t packh2(float a, float b) {
    uint32_t r;
    asm("cvt.rn.f16x2.f32 %0, %2, %1;" : "=r"(r) : "f"(a), "f"(b));
    return r;
}

// ---------------------------------------------------------------------------
// Prep: cp fp32 (seen as [k][o], k = i*12+c) -> lane-contiguous fp16 frags.
// ---------------------------------------------------------------------------
__global__ void bspline_prep_kernel(const float* __restrict__ cp) {
    int tid = blockIdx.x * blockDim.x + threadIdx.x;
    if (tid < KSTEPS * 2 * 32 * 2) {
        int q = tid & 1;
        int lid = (tid >> 1) & 31;
        int nb = (tid >> 6) & 1;
        int ks = tid >> 7;
        int n0 = nb * 32 + (lid >> 2) + q * 16;
        int k0 = ks * 16 + (lid & 3) * 2;
        uint4 v;
        v.x = packh2(cp[(k0 + 0) * 64 + n0],     cp[(k0 + 1) * 64 + n0]);
        v.y = packh2(cp[(k0 + 8) * 64 + n0],     cp[(k0 + 9) * 64 + n0]);
        v.z = packh2(cp[(k0 + 0) * 64 + n0 + 8], cp[(k0 + 1) * 64 + n0 + 8]);
        v.w = packh2(cp[(k0 + 8) * 64 + n0 + 8], cp[(k0 + 9) * 64 + n0 + 8]);
        g_Bf2[tid] = v;
    }
}

// ---------------------------------------------------------------------------
// Main kernel: one CTA = 64 rows, 8 warps = 4(M) x 2(N), warp tile M16xN32.
// ---------------------------------------------------------------------------
__global__ __launch_bounds__(THREADS, 2)
void bspline_hmma_kernel(const float* __restrict__ x,
                         float* __restrict__ out,
                         int nrows)
{
    extern __shared__ char sm[];
    const uint32_t sb = s2u(sm);
    const int t = threadIdx.x;
    const int wid = t >> 5;
    const int lid = t & 31;
    const int row0 = blockIdx.x * M_TILE;

    // Per-span table: {T[j-2..j+3], i1,i2a,i2b,i3a,i3b,i3c}, j = s+3
    float* tab = (float*)(sm + SMEM_TAB);
    if (t < 9) {
        const int j = t + 3;
        float* e = tab + t * 12;
        e[0] = knotv(j - 2); e[1] = knotv(j - 1); e[2] = knotv(j);
        e[3] = knotv(j + 1); e[4] = knotv(j + 2); e[5] = knotv(j + 3);
        e[6]  = 1.0f / (e[3] - e[2]);
        e[7]  = 1.0f / (e[3] - e[1]);
        e[8]  = 1.0f / (e[4] - e[2]);
        e[9]  = 1.0f / (e[3] - e[0]);
        e[10] = 1.0f / (e[4] - e[1]);
        e[11] = 1.0f / (e[5] - e[2]);
    }
    __syncthreads();

    // ---------------- Phase 1: build A tile in SMEM (fp16) ----------------
    // 64 rows x 16 i-quads = 1024 tasks, 4 per thread.
    #pragma unroll
    for (int s = 0; s < 4; s++) {
        const int p = s * THREADS + t;
        const int r = p >> 4;
        const int iq = p & 15;
        const int row = min(row0 + r, nrows - 1);

        const float4 xv = __ldg((const float4*)(x + (size_t)row * DIMS + iq * 4));
        const uint32_t wbase = sb + (uint32_t)r * A_PITCH_B + (uint32_t)iq * 96u;

        uint64_t keep0 = 0, keep1 = 0, keep2 = 0;
        #pragma unroll
        for (int u = 0; u < 4; u++) {
            float xc = (u == 0) ? xv.x : (u == 1) ? xv.y : (u == 2) ? xv.z : xv.w;
            xc = fminf(fmaxf(xc, 0.0f), 1.0f);

            const int s9 = min(8, (int)(xc * 9.0f));
            const float4* tb = (const float4*)(tab + s9 * 12);
            const float4 t0 = tb[0];
            const float4 t1 = tb[1];
            const float4 t2 = tb[2];

            const float l1 = xc - t0.z, r1 = t0.w - xc;
            const float l2 = xc - t0.y, r2 = t1.x - xc;
            const float l3 = xc - t0.x, r3 = t1.y - xc;

            float N0, N1, N2, N3, tmp, sv;
            tmp = t1.z;
            N0 = r1 * tmp; N1 = l1 * tmp;
            tmp = N0 * t1.w;
            N0 = r1 * tmp; sv = l2 * tmp;
            tmp = N1 * t2.x;
            N1 = fmaf(r2, tmp, sv); N2 = l1 * tmp;
            tmp = N0 * t2.y;
            N0 = r1 * tmp; sv = l3 * tmp;
            tmp = N1 * t2.z;
            N1 = fmaf(r2, tmp, sv); sv = l2 * tmp;
            tmp = N2 * t2.w;
            N2 = fmaf(r3, tmp, sv); N3 = l1 * tmp;

            const uint64_t w64 = (uint64_t)packh2(N0, N1)
                               | ((uint64_t)packh2(N2, N3) << 32);
            const int sl = s9 >> 2;
            const int rs = (s9 & 3) * 16;
            const uint64_t lo = w64 << rs;
            const uint64_t hi = rs ? (w64 >> (64 - rs)) : 0ULL;

            const uint64_t a0 = (sl == 0) ? lo : 0ULL;
            const uint64_t a1 = (sl == 1) ? lo : ((sl == 0) ? hi : 0ULL);
            const uint64_t a2 = (sl == 2) ? lo : ((sl == 1) ? hi : 0ULL);

            if ((u & 1) == 0) {
                keep0 = a0; keep1 = a1; keep2 = a2;
            } else {
                const uint32_t base = wbase + (uint32_t)(u >> 1) * 48u;
                asm volatile("st.shared.v2.u64 [%0], {%1, %2};"
                             :: "r"(base),      "l"(keep0), "l"(keep1) : "memory");
                asm volatile("st.shared.v2.u64 [%0], {%1, %2};"
                             :: "r"(base + 16), "l"(keep2), "l"(a0) : "memory");
                asm volatile("st.shared.v2.u64 [%0], {%1, %2};"
                             :: "r"(base + 32), "l"(a1), "l"(a2) : "memory");
            }
        }
    }
    __syncthreads();

    // ---------------- Phase 2: mma.sync mainloop (pipelined) ----------------
    const int mbase = (wid >> 1) * 16;      // 0,16,32,48
    const int nb    = wid & 1;              // N group -> nbase = nb*32

    const int lrow = (lid & 7) + ((lid >> 3) & 1) * 8;
    const int lcol = (lid >> 4) * 16;
    const uint32_t aAddr = sb + (uint32_t)(mbase + lrow) * A_PITCH_B + lcol;

    const uint4* __restrict__ Bf = g_Bf2 + (size_t)((nb * 32 + lid) * 2);

    float acc[4][4];
    #pragma unroll
    for (int nt = 0; nt < 4; nt++)
        #pragma unroll
        for (int q = 0; q < 4; q++) acc[nt][q] = 0.0f;

    uint32_t a[2][4];
    uint4 bb[2][2];

    // prologue: stage ks=0
    ldsm_x4(a[0][0], a[0][1], a[0][2], a[0][3], aAddr);
    bb[0][0] = __ldg(Bf + 0);
    bb[0][1] = __ldg(Bf + 1);

    #pragma unroll 4
    for (int ks = 0; ks < KSTEPS; ks++) {
        const int cur = ks & 1;
        const int nxt = cur ^ 1;
        if (ks + 1 < KSTEPS) {
            ldsm_x4(a[nxt][0], a[nxt][1], a[nxt][2], a[nxt][3],
                    aAddr + (ks + 1) * 32);
            bb[nxt][0] = __ldg(Bf + (ks + 1) * 128 + 0);
            bb[nxt][1] = __ldg(Bf + (ks + 1) * 128 + 1);
        }
        const uint32_t b0[4] = { bb[cur][0].x, bb[cur][0].z, bb[cur][1].x, bb[cur][1].z };
        const uint32_t b1[4] = { bb[cur][0].y, bb[cur][0].w, bb[cur][1].y, bb[cur][1].w };
        #pragma unroll
        for (int nt = 0; nt < 4; nt++)
            mma16816(acc[nt][0], acc[nt][1], acc[nt][2], acc[nt][3],
                     a[cur][0], a[cur][1], a[cur][2], a[cur][3],
                     b0[nt], b1[nt]);
    }

    // ---------------- Epilogue: direct float2 stores ----------------
    const int rquad = lid >> 2;
    const int npair = (lid & 3) * 2;
    #pragma unroll
    for (int nt = 0; nt < 4; nt++) {
        const int col = nb * 32 + nt * 8 + npair;
        const int rA = row0 + mbase + rquad;
        const int rB = rA + 8;
        if (rA < nrows)
            *(float2*)(out + (size_t)rA * DIMS + col) = make_float2(acc[nt][0], acc[nt][1]);
        if (rB < nrows)
            *(float2*)(out + (size_t)rB * DIMS + col) = make_float2(acc[nt][2], acc[nt][3]);
    }
}

extern "C" void kernel_launch(void* const* d_in, const int* in_sizes, int n_in,
                              void* d_out, int out_size)
{
    const float* x  = (const float*)d_in[0];   // (65536, 64)
    const float* cp = (const float*)d_in[1];   // (64, 12, 64) == B[768][64]
    float* out = (float*)d_out;

    const int nrows = in_sizes[0] / DIMS;

    bspline_prep_kernel<<<(KSTEPS * 2 * 32 * 2 + 255) / 256, 256>>>(cp);

    cudaFuncSetAttribute(bspline_hmma_kernel,
                         cudaFuncAttributeMaxDynamicSharedMemorySize, SMEM_TOTAL);
    const int grid = (nrows + M_TILE - 1) / M_TILE;
    bspline_hmma_kernel<<<grid, THREADS, SMEM_TOTAL>>>(x, out, nrows);
}

// round 8
// speedup vs baseline: 1.2589x; 1.2589x over previous
#include <cuda_runtime.h>
#include <cuda_fp16.h>
#include <cstdint>

// ============================================================================
// BSpline via warp-level mma.sync (HMMA).
//   out[b,o] = sum_{i,c} basis(x[b,i])[c] * cp[i,c,o]
//   = GEMM: A (rows x 768) * B (768 x 64), k = i*12 + c.
// R8 = R5 layouts (g_Bf uint2, A pitch 1552, table recips, depth-1 pipeline)
//   but THREADS=512, warp grid 4(M)x4(N), warp tile M16xN16:
//   2 CTA/SM x 16 warps = 32 warps/SM (occ ~46%) for latency hiding.
// ============================================================================

#define DIMS 64
#define KSTEPS 48          // 768 / 16
#define M_TILE 64
#define THREADS 512

#define A_PITCH_B 1552     // bytes per A row: 776 halfs; odd multiple of 16B
#define SMEM_A_BYTES (M_TILE * A_PITCH_B)        // 99328
#define SMEM_TAB SMEM_A_BYTES
#define SMEM_TOTAL (SMEM_A_BYTES + 512)

// B fragments: [kstep][n][kq] -> uint2 {h(k0),h(k0+1) | h(k0+8),h(k0+9)}
// k0 = kstep*16 + kq*2, value = cp[k][n].
__device__ uint2 g_Bf[KSTEPS * 64 * 4];

static __device__ __forceinline__ uint32_t s2u(const void* p) {
    uint32_t a;
    asm("{ .reg .u64 t; cvta.to.shared.u64 t, %1; cvt.u32.u64 %0, t; }" : "=r"(a) : "l"(p));
    return a;
}

static __device__ __forceinline__ void ldsm_x4(uint32_t& r0, uint32_t& r1,
                                               uint32_t& r2, uint32_t& r3,
                                               uint32_t addr) {
    asm volatile("ldmatrix.sync.aligned.m8n8.x4.shared.b16 {%0,%1,%2,%3}, [%4];"
                 : "=r"(r0), "=r"(r1), "=r"(r2), "=r"(r3) : "r"(addr));
}

static __device__ __forceinline__ void mma16816(float& d0, float& d1, float& d2, float& d3,
                                                uint32_t a0, uint32_t a1, uint32_t a2, uint32_t a3,
                                                uint32_t b0, uint32_t b1) {
    asm("mma.sync.aligned.m16n8k16.row.col.f32.f16.f16.f32 "
        "{%0,%1,%2,%3}, {%4,%5,%6,%7}, {%8,%9}, {%0,%1,%2,%3};"
        : "+f"(d0), "+f"(d1), "+f"(d2), "+f"(d3)
        : "r"(a0), "r"(a1), "r"(a2), "r"(a3), "r"(b0), "r"(b1));
}

static __device__ __forceinline__ float knotv(int k) {
    int v = max(0, min(9, k - 3));
    return (float)v / 9.0f;
}

static __device__ __forceinline__ uint32_t packh2(float a, float b) {
    uint32_t r;
    asm("cvt.rn.f16x2.f32 %0, %2, %1;" : "=r"(r) : "f"(a), "f"(b));
    return r;
}

// ---------------------------------------------------------------------------
// Prep: cp fp32 (seen as [k][o], k = i*12+c) -> fragment-ordered fp16 g_Bf.
// ---------------------------------------------------------------------------
__global__ void bspline_prep_kernel(const float* __restrict__ cp) {
    int tid = blockIdx.x * blockDim.x + threadIdx.x;
    if (tid < KSTEPS * 64 * 4) {
        int kq = tid & 3;
        int n = (tid >> 2) & 63;
        int kstep = tid >> 8;
        int k0 = kstep * 16 + kq * 2;
        uint2 v;
        v.x = packh2(cp[(k0 + 0) * 64 + n], cp[(k0 + 1) * 64 + n]);
        v.y = packh2(cp[(k0 + 8) * 64 + n], cp[(k0 + 9) * 64 + n]);
        g_Bf[tid] = v;
    }
}

// ---------------------------------------------------------------------------
// Main kernel: one CTA = 64 rows, 16 warps = 4(M) x 4(N), warp tile M16xN16.
// ---------------------------------------------------------------------------
__global__ __launch_bounds__(THREADS, 2)
void bspline_hmma_kernel(const float* __restrict__ x,
                         float* __restrict__ out,
                         int nrows)
{
    extern __shared__ char sm[];
    const uint32_t sb = s2u(sm);
    const int t = threadIdx.x;
    const int wid = t >> 5;
    const int lid = t & 31;
    const int row0 = blockIdx.x * M_TILE;

    // Per-span table: {T[j-2..j+3], i1,i2a,i2b,i3a,i3b,i3c}, j = s+3
    float* tab = (float*)(sm + SMEM_TAB);
    if (t < 9) {
        const int j = t + 3;
        float* e = tab + t * 12;
        e[0] = knotv(j - 2); e[1] = knotv(j - 1); e[2] = knotv(j);
        e[3] = knotv(j + 1); e[4] = knotv(j + 2); e[5] = knotv(j + 3);
        e[6]  = 1.0f / (e[3] - e[2]);
        e[7]  = 1.0f / (e[3] - e[1]);
        e[8]  = 1.0f / (e[4] - e[2]);
        e[9]  = 1.0f / (e[3] - e[0]);
        e[10] = 1.0f / (e[4] - e[1]);
        e[11] = 1.0f / (e[5] - e[2]);
    }
    __syncthreads();

    // ---------------- Phase 1: build A tile in SMEM (fp16) ----------------
    // 64 rows x 16 i-quads = 1024 tasks, 2 per thread.
    #pragma unroll
    for (int s = 0; s < 2; s++) {
        const int p = s * THREADS + t;
        const int r = p >> 4;
        const int iq = p & 15;
        const int row = min(row0 + r, nrows - 1);

        const float4 xv = __ldg((const float4*)(x + (size_t)row * DIMS + iq * 4));
        const uint32_t wbase = sb + (uint32_t)r * A_PITCH_B + (uint32_t)iq * 96u;

        uint64_t keep0 = 0, keep1 = 0, keep2 = 0;
        #pragma unroll
        for (int u = 0; u < 4; u++) {
            float xc = (u == 0) ? xv.x : (u == 1) ? xv.y : (u == 2) ? xv.z : xv.w;
            xc = fminf(fmaxf(xc, 0.0f), 1.0f);

            const int s9 = min(8, (int)(xc * 9.0f));
            const float4* tb = (const float4*)(tab + s9 * 12);
            const float4 t0 = tb[0];
            const float4 t1 = tb[1];
            const float4 t2 = tb[2];

            const float l1 = xc - t0.z, r1 = t0.w - xc;
            const float l2 = xc - t0.y, r2 = t1.x - xc;
            const float l3 = xc - t0.x, r3 = t1.y - xc;

            float N0, N1, N2, N3, tmp, sv;
            tmp = t1.z;
            N0 = r1 * tmp; N1 = l1 * tmp;
            tmp = N0 * t1.w;
            N0 = r1 * tmp; sv = l2 * tmp;
            tmp = N1 * t2.x;
            N1 = fmaf(r2, tmp, sv); N2 = l1 * tmp;
            tmp = N0 * t2.y;
            N0 = r1 * tmp; sv = l3 * tmp;
            tmp = N1 * t2.z;
            N1 = fmaf(r2, tmp, sv); sv = l2 * tmp;
            tmp = N2 * t2.w;
            N2 = fmaf(r3, tmp, sv); N3 = l1 * tmp;

            const uint64_t w64 = (uint64_t)packh2(N0, N1)
                               | ((uint64_t)packh2(N2, N3) << 32);
            const int sl = s9 >> 2;
            const int rs = (s9 & 3) * 16;
            const uint64_t lo = w64 << rs;
            const uint64_t hi = rs ? (w64 >> (64 - rs)) : 0ULL;

            const uint64_t a0 = (sl == 0) ? lo : 0ULL;
            const uint64_t a1 = (sl == 1) ? lo : ((sl == 0) ? hi : 0ULL);
            const uint64_t a2 = (sl == 2) ? lo : ((sl == 1) ? hi : 0ULL);

            if ((u & 1) == 0) {
                keep0 = a0; keep1 = a1; keep2 = a2;
            } else {
                const uint32_t base = wbase + (uint32_t)(u >> 1) * 48u;
                asm volatile("st.shared.v2.u64 [%0], {%1, %2};"
                             :: "r"(base),      "l"(keep0), "l"(keep1) : "memory");
                asm volatile("st.shared.v2.u64 [%0], {%1, %2};"
                             :: "r"(base + 16), "l"(keep2), "l"(a0) : "memory");
                asm volatile("st.shared.v2.u64 [%0], {%1, %2};"
                             :: "r"(base + 32), "l"(a1), "l"(a2) : "memory");
            }
        }
    }
    __syncthreads();

    // ---------------- Phase 2: mma.sync mainloop (pipelined) ----------------
    const int mbase = (wid >> 2) * 16;      // 0,16,32,48
    const int nbase = (wid & 3) * 16;       // 0,16,32,48

    const int lrow = (lid & 7) + ((lid >> 3) & 1) * 8;
    const int lcol = (lid >> 4) * 16;
    const uint32_t aAddr = sb + (uint32_t)(mbase + lrow) * A_PITCH_B + lcol;

    const uint2* __restrict__ Bf = g_Bf;
    const int bLane = (nbase + (lid >> 2)) * 4 + (lid & 3);

    float acc[2][4];
    #pragma unroll
    for (int nt = 0; nt < 2; nt++)
        #pragma unroll
        for (int q = 0; q < 4; q++) acc[nt][q] = 0.0f;

    uint32_t a[2][4];
    uint2 b[2][2];

    // prologue: stage ks=0
    ldsm_x4(a[0][0], a[0][1], a[0][2], a[0][3], aAddr);
    b[0][0] = __ldg(Bf + bLane);
    b[0][1] = __ldg(Bf + bLane + 32);

    #pragma unroll 4
    for (int ks = 0; ks < KSTEPS; ks++) {
        const int cur = ks & 1;
        const int nxt = cur ^ 1;
        if (ks + 1 < KSTEPS) {
            ldsm_x4(a[nxt][0], a[nxt][1], a[nxt][2], a[nxt][3],
                    aAddr + (ks + 1) * 32);
            const int bi = (ks + 1) * 256 + bLane;
            b[nxt][0] = __ldg(Bf + bi);
            b[nxt][1] = __ldg(Bf + bi + 32);
        }
        #pragma unroll
        for (int nt = 0; nt < 2; nt++)
            mma16816(acc[nt][0], acc[nt][1], acc[nt][2], acc[nt][3],
                     a[cur][0], a[cur][1], a[cur][2], a[cur][3],
                     b[cur][nt].x, b[cur][nt].y);
    }

    // ---------------- Epilogue: direct float2 stores ----------------
    const int rquad = lid >> 2;
    const int npair = (lid & 3) * 2;
    #pragma unroll
    for (int nt = 0; nt < 2; nt++) {
        const int col = nbase + nt * 8 + npair;
        const int rA = row0 + mbase + rquad;
        const int rB = rA + 8;
        if (rA < nrows)
            *(float2*)(out + (size_t)rA * DIMS + col) = make_float2(acc[nt][0], acc[nt][1]);
        if (rB < nrows)
            *(float2*)(out + (size_t)rB * DIMS + col) = make_float2(acc[nt][2], acc[nt][3]);
    }
}

extern "C" void kernel_launch(void* const* d_in, const int* in_sizes, int n_in,
                              void* d_out, int out_size)
{
    const float* x  = (const float*)d_in[0];   // (65536, 64)
    const float* cp = (const float*)d_in[1];   // (64, 12, 64) == B[768][64]
    float* out = (float*)d_out;

    const int nrows = in_sizes[0] / DIMS;

    bspline_prep_kernel<<<(KSTEPS * 64 * 4 + 255) / 256, 256>>>(cp);

    cudaFuncSetAttribute(bspline_hmma_kernel,
                         cudaFuncAttributeMaxDynamicSharedMemorySize, SMEM_TOTAL);
    const int grid = (nrows + M_TILE - 1) / M_TILE;
    bspline_hmma_kernel<<<grid, THREADS, SMEM_TOTAL>>>(x, out, nrows);
}

// round 9
// speedup vs baseline: 1.4238x; 1.1310x over previous
#include <cuda_runtime.h>
#include <cuda_fp16.h>
#include <cstdint>

// ============================================================================
// BSpline via warp-level mma.sync (HMMA).
//   out[b,o] = sum_{i,c} basis(x[b,i])[c] * cp[i,c,o]
//   = GEMM: A (rows x 768) * B (768 x 64), k = i*12 + c.
// R9: warp tile M16xN32 (halves A-LDSM redundancy vs R8) at the SAME
//   32 warps/SM: A tile k-split into 2 passes of K=384 -> SMEM 50KB ->
//   4 CTA/SM x 8 warps. Accumulators persist in registers across passes.
//   B fragments in the proven R5 uint2 layout.
// ============================================================================

#define DIMS 64
#define KSTEPS 48          // 768 / 16
#define KS_PASS 24         // ksteps per pass
#define M_TILE 64
#define THREADS 256

#define A_PITCH_B 784      // bytes per A row per pass: 392 halfs (odd x 16B)
#define SMEM_A_BYTES (M_TILE * A_PITCH_B)        // 50176
#define SMEM_TAB SMEM_A_BYTES
#define SMEM_TOTAL (SMEM_A_BYTES + 512)

// B fragments: [kstep][n][kq] -> uint2 {h(k0),h(k0+1) | h(k0+8),h(k0+9)}
// k0 = kstep*16 + kq*2, value = cp[k][n].
__device__ uint2 g_Bf[KSTEPS * 64 * 4];

static __device__ __forceinline__ uint32_t s2u(const void* p) {
    uint32_t a;
    asm("{ .reg .u64 t; cvta.to.shared.u64 t, %1; cvt.u32.u64 %0, t; }" : "=r"(a) : "l"(p));
    return a;
}

static __device__ __forceinline__ void ldsm_x4(uint32_t& r0, uint32_t& r1,
                                               uint32_t& r2, uint32_t& r3,
                                               uint32_t addr) {
    asm volatile("ldmatrix.sync.aligned.m8n8.x4.shared.b16 {%0,%1,%2,%3}, [%4];"
                 : "=r"(r0), "=r"(r1), "=r"(r2), "=r"(r3) : "r"(addr));
}

static __device__ __forceinline__ void mma16816(float& d0, float& d1, float& d2, float& d3,
                                                uint32_t a0, uint32_t a1, uint32_t a2, uint32_t a3,
                                                uint32_t b0, uint32_t b1) {
    asm("mma.sync.aligned.m16n8k16.row.col.f32.f16.f16.f32 "
        "{%0,%1,%2,%3}, {%4,%5,%6,%7}, {%8,%9}, {%0,%1,%2,%3};"
        : "+f"(d0), "+f"(d1), "+f"(d2), "+f"(d3)
        : "r"(a0), "r"(a1), "r"(a2), "r"(a3), "r"(b0), "r"(b1));
}

static __device__ __forceinline__ float knotv(int k) {
    int v = max(0, min(9, k - 3));
    return (float)v / 9.0f;
}

static __device__ __forceinline__ uint32_t packh2(float a, float b) {
    uint32_t r;
    asm("cvt.rn.f16x2.f32 %0, %2, %1;" : "=r"(r) : "f"(a), "f"(b));
    return r;
}

// ---------------------------------------------------------------------------
// Prep: cp fp32 (seen as [k][o], k = i*12+c) -> fragment-ordered fp16 g_Bf.
// ---------------------------------------------------------------------------
__global__ void bspline_prep_kernel(const float* __restrict__ cp) {
    int tid = blockIdx.x * blockDim.x + threadIdx.x;
    if (tid < KSTEPS * 64 * 4) {
        int kq = tid & 3;
        int n = (tid >> 2) & 63;
        int kstep = tid >> 8;
        int k0 = kstep * 16 + kq * 2;
        uint2 v;
        v.x = packh2(cp[(k0 + 0) * 64 + n], cp[(k0 + 1) * 64 + n]);
        v.y = packh2(cp[(k0 + 8) * 64 + n], cp[(k0 + 9) * 64 + n]);
        g_Bf[tid] = v;
    }
}

// ---------------------------------------------------------------------------
// Main kernel: one CTA = 64 rows, 8 warps = 4(M) x 2(N), warp tile M16xN32.
// K processed in 2 passes of 384 (i in [32p, 32p+32), ksteps [24p, 24p+24)).
// ---------------------------------------------------------------------------
__global__ __launch_bounds__(THREADS, 4)
void bspline_hmma_kernel(const float* __restrict__ x,
                         float* __restrict__ out,
                         int nrows)
{
    extern __shared__ char sm[];
    const uint32_t sb = s2u(sm);
    const int t = threadIdx.x;
    const int wid = t >> 5;
    const int lid = t & 31;
    const int row0 = blockIdx.x * M_TILE;

    // Per-span table: {T[j-2..j+3], i1,i2a,i2b,i3a,i3b,i3c}, j = s+3
    float* tab = (float*)(sm + SMEM_TAB);
    if (t < 9) {
        const int j = t + 3;
        float* e = tab + t * 12;
        e[0] = knotv(j - 2); e[1] = knotv(j - 1); e[2] = knotv(j);
        e[3] = knotv(j + 1); e[4] = knotv(j + 2); e[5] = knotv(j + 3);
        e[6]  = 1.0f / (e[3] - e[2]);
        e[7]  = 1.0f / (e[3] - e[1]);
        e[8]  = 1.0f / (e[4] - e[2]);
        e[9]  = 1.0f / (e[3] - e[0]);
        e[10] = 1.0f / (e[4] - e[1]);
        e[11] = 1.0f / (e[5] - e[2]);
    }

    // Warp-tile constants (stable across passes)
    const int mbase = (wid >> 1) * 16;      // 0,16,32,48
    const int nb    = wid & 1;              // N group -> nbase = nb*32
    const int lrow = (lid & 7) + ((lid >> 3) & 1) * 8;
    const int lcol = (lid >> 4) * 16;
    const uint32_t aAddr = sb + (uint32_t)(mbase + lrow) * A_PITCH_B + lcol;
    const uint2* __restrict__ Bf = g_Bf;
    const int bLane = (nb * 32 + (lid >> 2)) * 4 + (lid & 3);

    float acc[4][4];
    #pragma unroll
    for (int nt = 0; nt < 4; nt++)
        #pragma unroll
        for (int q = 0; q < 4; q++) acc[nt][q] = 0.0f;

    #pragma unroll
    for (int pass = 0; pass < 2; pass++) {
        __syncthreads();   // pass 0: after table init; pass 1: A-tile WAR

        // ------------- Build phase: i in [32*pass, 32*pass+32) -------------
        // 64 rows x 8 i-quads = 512 tasks, 2 per thread.
        #pragma unroll
        for (int s = 0; s < 2; s++) {
            const int p = s * THREADS + t;
            const int r = p >> 3;               // row in tile
            const int iql = p & 7;              // local i-quad (0..7)
            const int row = min(row0 + r, nrows - 1);

            const float4 xv = __ldg((const float4*)(
                x + (size_t)row * DIMS + (pass * 8 + iql) * 4));
            const uint32_t wbase = sb + (uint32_t)r * A_PITCH_B + (uint32_t)iql * 96u;

            #pragma unroll
            for (int u = 0; u < 4; u++) {
                float xc = (u == 0) ? xv.x : (u == 1) ? xv.y : (u == 2) ? xv.z : xv.w;
                xc = fminf(fmaxf(xc, 0.0f), 1.0f);

                const int s9 = min(8, (int)(xc * 9.0f));
                const float4* tb = (const float4*)(tab + s9 * 12);
                const float4 t0 = tb[0];
                const float4 t1 = tb[1];
                const float4 t2 = tb[2];

                const float l1 = xc - t0.z, r1 = t0.w - xc;
                const float l2 = xc - t0.y, r2 = t1.x - xc;
                const float l3 = xc - t0.x, r3 = t1.y - xc;

                float N0, N1, N2, N3, tmp, sv;
                tmp = t1.z;
                N0 = r1 * tmp; N1 = l1 * tmp;
                tmp = N0 * t1.w;
                N0 = r1 * tmp; sv = l2 * tmp;
                tmp = N1 * t2.x;
                N1 = fmaf(r2, tmp, sv); N2 = l1 * tmp;
                tmp = N0 * t2.y;
                N0 = r1 * tmp; sv = l3 * tmp;
                tmp = N1 * t2.z;
                N1 = fmaf(r2, tmp, sv); sv = l2 * tmp;
                tmp = N2 * t2.w;
                N2 = fmaf(r3, tmp, sv); N3 = l1 * tmp;

                const uint64_t w64 = (uint64_t)packh2(N0, N1)
                                   | ((uint64_t)packh2(N2, N3) << 32);
                const int sl = s9 >> 2;
                const int rs = (s9 & 3) * 16;
                const uint64_t lo = w64 << rs;
                const uint64_t hi = rs ? (w64 >> (64 - rs)) : 0ULL;

                const uint64_t a0 = (sl == 0) ? lo : 0ULL;
                const uint64_t a1 = (sl == 1) ? lo : ((sl == 0) ? hi : 0ULL);
                const uint64_t a2 = (sl == 2) ? lo : ((sl == 1) ? hi : 0ULL);

                const uint32_t w = wbase + (uint32_t)u * 24u;
                asm volatile("st.shared.u64 [%0], %1;" :: "r"(w),      "l"(a0) : "memory");
                asm volatile("st.shared.u64 [%0], %1;" :: "r"(w + 8),  "l"(a1) : "memory");
                asm volatile("st.shared.u64 [%0], %1;" :: "r"(w + 16), "l"(a2) : "memory");
            }
        }
        __syncthreads();

        // ------------- MMA phase: ksteps [24*pass, 24*pass+24) -------------
        uint32_t a[2][4];
        uint2 b[2][4];

        const int ksg0 = pass * KS_PASS;
        ldsm_x4(a[0][0], a[0][1], a[0][2], a[0][3], aAddr);
        {
            const int bi = ksg0 * 256 + bLane;
            #pragma unroll
            for (int nt = 0; nt < 4; nt++) b[0][nt] = __ldg(Bf + bi + nt * 32);
        }

        #pragma unroll 4
        for (int ksl = 0; ksl < KS_PASS; ksl++) {
            const int cur = ksl & 1;
            const int nxt = cur ^ 1;
            if (ksl + 1 < KS_PASS) {
                ldsm_x4(a[nxt][0], a[nxt][1], a[nxt][2], a[nxt][3],
                        aAddr + (ksl + 1) * 32);
                const int bi = (ksg0 + ksl + 1) * 256 + bLane;
                #pragma unroll
                for (int nt = 0; nt < 4; nt++) b[nxt][nt] = __ldg(Bf + bi + nt * 32);
            }
            #pragma unroll
            for (int nt = 0; nt < 4; nt++)
                mma16816(acc[nt][0], acc[nt][1], acc[nt][2], acc[nt][3],
                         a[cur][0], a[cur][1], a[cur][2], a[cur][3],
                         b[cur][nt].x, b[cur][nt].y);
        }
    }

    // ---------------- Epilogue: direct float2 stores ----------------
    const int rquad = lid >> 2;
    const int npair = (lid & 3) * 2;
    #pragma unroll
    for (int nt = 0; nt < 4; nt++) {
        const int col = nb * 32 + nt * 8 + npair;
        const int rA = row0 + mbase + rquad;
        const int rB = rA + 8;
        if (rA < nrows)
            *(float2*)(out + (size_t)rA * DIMS + col) = make_float2(acc[nt][0], acc[nt][1]);
        if (rB < nrows)
            *(float2*)(out + (size_t)rB * DIMS + col) = make_float2(acc[nt][2], acc[nt][3]);
    }
}

extern "C" void kernel_launch(void* const* d_in, const int* in_sizes, int n_in,
                              void* d_out, int out_size)
{
    const float* x  = (const float*)d_in[0];   // (65536, 64)
    const float* cp = (const float*)d_in[1];   // (64, 12, 64) == B[768][64]
    float* out = (float*)d_out;

    const int nrows = in_sizes[0] / DIMS;

    bspline_prep_kernel<<<(KSTEPS * 64 * 4 + 255) / 256, 256>>>(cp);

    cudaFuncSetAttribute(bspline_hmma_kernel,
                         cudaFuncAttributeMaxDynamicSharedMemorySize, SMEM_TOTAL);
    const int grid = (nrows + M_TILE - 1) / M_TILE;
    bspline_hmma_kernel<<<grid, THREADS, SMEM_TOTAL>>>(x, out, nrows);
}

// round 10
// speedup vs baseline: 1.4828x; 1.0414x over previous
#include <cuda_runtime.h>
#include <cuda_fp16.h>
#include <cstdint>

// ============================================================================
// BSpline via warp-level mma.sync (HMMA).
//   out[b,o] = sum_{i,c} basis(x[b,i])[c] * cp[i,c,o]
//   = GEMM: A (rows x 768) * B (768 x 64), k = i*12 + c.
// R10: A tile k-split into 4 passes of K=192 -> SMEM 25.6KB/CTA -> 4 CTA/SM
//   uses only ~104KB smem, leaving ~124KB L1D so the 98KB B-fragment table
//   is L1-resident (was thrashing to L2 at ~240cyc). 32 warps/SM unchanged.
// ============================================================================

#define DIMS 64
#define KSTEPS 48          // 768 / 16
#define NPASS 4
#define KS_PASS 12         // ksteps per pass
#define M_TILE 64
#define THREADS 256

#define A_PITCH_B 400      // bytes per A row per pass: 16 windows*24B pad->400 (odd x 16B)
#define SMEM_A_BYTES (M_TILE * A_PITCH_B)        // 25600
#define SMEM_TAB SMEM_A_BYTES
#define SMEM_TOTAL (SMEM_A_BYTES + 512)

// B fragments: [kstep][n][kq] -> uint2 {h(k0),h(k0+1) | h(k0+8),h(k0+9)}
// k0 = kstep*16 + kq*2, value = cp[k][n].
__device__ uint2 g_Bf[KSTEPS * 64 * 4];

static __device__ __forceinline__ uint32_t s2u(const void* p) {
    uint32_t a;
    asm("{ .reg .u64 t; cvta.to.shared.u64 t, %1; cvt.u32.u64 %0, t; }" : "=r"(a) : "l"(p));
    return a;
}

static __device__ __forceinline__ void ldsm_x4(uint32_t& r0, uint32_t& r1,
                                               uint32_t& r2, uint32_t& r3,
                                               uint32_t addr) {
    asm volatile("ldmatrix.sync.aligned.m8n8.x4.shared.b16 {%0,%1,%2,%3}, [%4];"
                 : "=r"(r0), "=r"(r1), "=r"(r2), "=r"(r3) : "r"(addr));
}

static __device__ __forceinline__ void mma16816(float& d0, float& d1, float& d2, float& d3,
                                                uint32_t a0, uint32_t a1, uint32_t a2, uint32_t a3,
                                                uint32_t b0, uint32_t b1) {
    asm("mma.sync.aligned.m16n8k16.row.col.f32.f16.f16.f32 "
        "{%0,%1,%2,%3}, {%4,%5,%6,%7}, {%8,%9}, {%0,%1,%2,%3};"
        : "+f"(d0), "+f"(d1), "+f"(d2), "+f"(d3)
        : "r"(a0), "r"(a1), "r"(a2), "r"(a3), "r"(b0), "r"(b1));
}

static __device__ __forceinline__ float knotv(int k) {
    int v = max(0, min(9, k - 3));
    return (float)v / 9.0f;
}

static __device__ __forceinline__ uint32_t packh2(float a, float b) {
    uint32_t r;
    asm("cvt.rn.f16x2.f32 %0, %2, %1;" : "=r"(r) : "f"(a), "f"(b));
    return r;
}

// ---------------------------------------------------------------------------
// Prep: cp fp32 (seen as [k][o], k = i*12+c) -> fragment-ordered fp16 g_Bf.
// ---------------------------------------------------------------------------
__global__ void bspline_prep_kernel(const float* __restrict__ cp) {
    int tid = blockIdx.x * blockDim.x + threadIdx.x;
    if (tid < KSTEPS * 64 * 4) {
        int kq = tid & 3;
        int n = (tid >> 2) & 63;
        int kstep = tid >> 8;
        int k0 = kstep * 16 + kq * 2;
        uint2 v;
        v.x = packh2(cp[(k0 + 0) * 64 + n], cp[(k0 + 1) * 64 + n]);
        v.y = packh2(cp[(k0 + 8) * 64 + n], cp[(k0 + 9) * 64 + n]);
        g_Bf[tid] = v;
    }
}

// ---------------------------------------------------------------------------
// Main kernel: one CTA = 64 rows, 8 warps = 4(M) x 2(N), warp tile M16xN32.
// K processed in 4 passes of 192 (i in [16p, 16p+16), ksteps [12p, 12p+12)).
// ---------------------------------------------------------------------------
__global__ __launch_bounds__(THREADS, 4)
void bspline_hmma_kernel(const float* __restrict__ x,
                         float* __restrict__ out,
                         int nrows)
{
    extern __shared__ char sm[];
    const uint32_t sb = s2u(sm);
    const int t = threadIdx.x;
    const int wid = t >> 5;
    const int lid = t & 31;
    const int row0 = blockIdx.x * M_TILE;

    // Per-span table: {T[j-2..j+3], i1,i2a,i2b,i3a,i3b,i3c}, j = s+3
    float* tab = (float*)(sm + SMEM_TAB);
    if (t < 9) {
        const int j = t + 3;
        float* e = tab + t * 12;
        e[0] = knotv(j - 2); e[1] = knotv(j - 1); e[2] = knotv(j);
        e[3] = knotv(j + 1); e[4] = knotv(j + 2); e[5] = knotv(j + 3);
        e[6]  = 1.0f / (e[3] - e[2]);
        e[7]  = 1.0f / (e[3] - e[1]);
        e[8]  = 1.0f / (e[4] - e[2]);
        e[9]  = 1.0f / (e[3] - e[0]);
        e[10] = 1.0f / (e[4] - e[1]);
        e[11] = 1.0f / (e[5] - e[2]);
    }

    // Warp-tile constants (stable across passes)
    const int mbase = (wid >> 1) * 16;      // 0,16,32,48
    const int nb    = wid & 1;              // N group -> nbase = nb*32
    const int lrow = (lid & 7) + ((lid >> 3) & 1) * 8;
    const int lcol = (lid >> 4) * 16;
    const uint32_t aAddr = sb + (uint32_t)(mbase + lrow) * A_PITCH_B + lcol;
    const uint2* __restrict__ Bf = g_Bf;
    const int bLane = (nb * 32 + (lid >> 2)) * 4 + (lid & 3);

    float acc[4][4];
    #pragma unroll
    for (int nt = 0; nt < 4; nt++)
        #pragma unroll
        for (int q = 0; q < 4; q++) acc[nt][q] = 0.0f;

    #pragma unroll
    for (int pass = 0; pass < NPASS; pass++) {
        __syncthreads();   // pass 0: after table init; later: A-tile WAR

        // ------------- Build phase: i in [16*pass, 16*pass+16) -------------
        // 64 rows x 4 i-quads = 256 tasks, 1 per thread.
        {
            const int r = t >> 2;               // row in tile
            const int iql = t & 3;              // local i-quad (0..3)
            const int row = min(row0 + r, nrows - 1);

            const float4 xv = __ldg((const float4*)(
                x + (size_t)row * DIMS + (pass * 4 + iql) * 4));
            const uint32_t wbase = sb + (uint32_t)r * A_PITCH_B + (uint32_t)iql * 96u;

            #pragma unroll
            for (int u = 0; u < 4; u++) {
                float xc = (u == 0) ? xv.x : (u == 1) ? xv.y : (u == 2) ? xv.z : xv.w;
                xc = fminf(fmaxf(xc, 0.0f), 1.0f);

                const int s9 = min(8, (int)(xc * 9.0f));
                const float4* tb = (const float4*)(tab + s9 * 12);
                const float4 t0 = tb[0];
                const float4 t1 = tb[1];
                const float4 t2 = tb[2];

                const float l1 = xc - t0.z, r1 = t0.w - xc;
                const float l2 = xc - t0.y, r2 = t1.x - xc;
                const float l3 = xc - t0.x, r3 = t1.y - xc;

                float N0, N1, N2, N3, tmp, sv;
                tmp = t1.z;
                N0 = r1 * tmp; N1 = l1 * tmp;
                tmp = N0 * t1.w;
                N0 = r1 * tmp; sv = l2 * tmp;
                tmp = N1 * t2.x;
                N1 = fmaf(r2, tmp, sv); N2 = l1 * tmp;
                tmp = N0 * t2.y;
                N0 = r1 * tmp; sv = l3 * tmp;
                tmp = N1 * t2.z;
                N1 = fmaf(r2, tmp, sv); sv = l2 * tmp;
                tmp = N2 * t2.w;
                N2 = fmaf(r3, tmp, sv); N3 = l1 * tmp;

                const uint64_t w64 = (uint64_t)packh2(N0, N1)
                                   | ((uint64_t)packh2(N2, N3) << 32);
                const int sl = s9 >> 2;
                const int rs = (s9 & 3) * 16;
                const uint64_t lo = w64 << rs;
                const uint64_t hi = rs ? (w64 >> (64 - rs)) : 0ULL;

                const uint64_t a0 = (sl == 0) ? lo : 0ULL;
                const uint64_t a1 = (sl == 1) ? lo : ((sl == 0) ? hi : 0ULL);
                const uint64_t a2 = (sl == 2) ? lo : ((sl == 1) ? hi : 0ULL);

                const uint32_t w = wbase + (uint32_t)u * 24u;
                asm volatile("st.shared.u64 [%0], %1;" :: "r"(w),      "l"(a0) : "memory");
                asm volatile("st.shared.u64 [%0], %1;" :: "r"(w + 8),  "l"(a1) : "memory");
                asm volatile("st.shared.u64 [%0], %1;" :: "r"(w + 16), "l"(a2) : "memory");
            }
        }
        __syncthreads();

        // ------------- MMA phase: ksteps [12*pass, 12*pass+12) -------------
        uint32_t a[2][4];
        uint2 b[2][4];

        const int ksg0 = pass * KS_PASS;
        ldsm_x4(a[0][0], a[0][1], a[0][2], a[0][3], aAddr);
        {
            const int bi = ksg0 * 256 + bLane;
            #pragma unroll
            for (int nt = 0; nt < 4; nt++) b[0][nt] = __ldg(Bf + bi + nt * 32);
        }

        #pragma unroll 4
        for (int ksl = 0; ksl < KS_PASS; ksl++) {
            const int cur = ksl & 1;
            const int nxt = cur ^ 1;
            if (ksl + 1 < KS_PASS) {
                ldsm_x4(a[nxt][0], a[nxt][1], a[nxt][2], a[nxt][3],
                        aAddr + (ksl + 1) * 32);
                const int bi = (ksg0 + ksl + 1) * 256 + bLane;
                #pragma unroll
                for (int nt = 0; nt < 4; nt++) b[nxt][nt] = __ldg(Bf + bi + nt * 32);
            }
            #pragma unroll
            for (int nt = 0; nt < 4; nt++)
                mma16816(acc[nt][0], acc[nt][1], acc[nt][2], acc[nt][3],
                         a[cur][0], a[cur][1], a[cur][2], a[cur][3],
                         b[cur][nt].x, b[cur][nt].y);
        }
    }

    // ---------------- Epilogue: direct float2 stores ----------------
    const int rquad = lid >> 2;
    const int npair = (lid & 3) * 2;
    #pragma unroll
    for (int nt = 0; nt < 4; nt++) {
        const int col = nb * 32 + nt * 8 + npair;
        const int rA = row0 + mbase + rquad;
        const int rB = rA + 8;
        if (rA < nrows)
            *(float2*)(out + (size_t)rA * DIMS + col) = make_float2(acc[nt][0], acc[nt][1]);
        if (rB < nrows)
            *(float2*)(out + (size_t)rB * DIMS + col) = make_float2(acc[nt][2], acc[nt][3]);
    }
}

extern "C" void kernel_launch(void* const* d_in, const int* in_sizes, int n_in,
                              void* d_out, int out_size)
{
    const float* x  = (const float*)d_in[0];   // (65536, 64)
    const float* cp = (const float*)d_in[1];   // (64, 12, 64) == B[768][64]
    float* out = (float*)d_out;

    const int nrows = in_sizes[0] / DIMS;

    bspline_prep_kernel<<<(KSTEPS * 64 * 4 + 255) / 256, 256>>>(cp);

    cudaFuncSetAttribute(bspline_hmma_kernel,
                         cudaFuncAttributeMaxDynamicSharedMemorySize, SMEM_TOTAL);
    const int grid = (nrows + M_TILE - 1) / M_TILE;
    bspline_hmma_kernel<<<grid, THREADS, SMEM_TOTAL>>>(x, out, nrows);
}